// round 17
// baseline (speedup 1.0000x reference)
#include <cuda_runtime.h>
#include <cuda.h>
#include <cuda_fp16.h>
#include <math.h>
#include <float.h>
#include <stdint.h>

#define BB 4
#define SS 2048
#define DD 1024

// ---------------------------------------------------------------------------
// Scratch (static device globals; runtime allocation is forbidden)
// ---------------------------------------------------------------------------
__device__ __half g_qh[BB * SS * DD];
__device__ __half g_kh[BB * SS * DD];
__device__ __half g_vth[BB * DD * SS];          // v transposed [b][d][s]
__device__ float  g_sc[(size_t)BB * SS * SS];   // raw scores
__device__ __half g_ph[(size_t)BB * SS * SS];   // softmax probs (fp16)

// ---------------------------------------------------------------------------
// PTX helpers (baseline ISA only — compute_103 safe)
// ---------------------------------------------------------------------------
__device__ __forceinline__ uint32_t smem_u32(const void* p) {
    uint32_t a;
    asm("{ .reg .u64 t; cvta.to.shared.u64 t, %1; cvt.u32.u64 %0, t; }"
        : "=r"(a) : "l"(p));
    return a;
}
__device__ __forceinline__ void ldsm_x4(uint32_t& r0, uint32_t& r1,
                                        uint32_t& r2, uint32_t& r3, uint32_t addr) {
    asm volatile("ldmatrix.sync.aligned.m8n8.x4.shared.b16 {%0,%1,%2,%3}, [%4];"
                 : "=r"(r0), "=r"(r1), "=r"(r2), "=r"(r3) : "r"(addr));
}
__device__ __forceinline__ void mma16816(float* c, const uint32_t* a, const uint32_t* b) {
    asm volatile(
        "mma.sync.aligned.m16n8k16.row.col.f32.f16.f16.f32 "
        "{%0,%1,%2,%3}, {%4,%5,%6,%7}, {%8,%9}, {%0,%1,%2,%3};"
        : "+f"(c[0]), "+f"(c[1]), "+f"(c[2]), "+f"(c[3])
        : "r"(a[0]), "r"(a[1]), "r"(a[2]), "r"(a[3]), "r"(b[0]), "r"(b[1]));
}
__device__ __forceinline__ void tma_load_3d(uint32_t smem_addr,
                                            const CUtensorMap* map,
                                            int cx, int cy, int cz,
                                            uint32_t mbar) {
    asm volatile(
        "cp.async.bulk.tensor.3d.shared::cta.global.tile.mbarrier::complete_tx::bytes "
        "[%0], [%1, {%2, %3, %4}], [%5];"
        :: "r"(smem_addr), "l"(map), "r"(cx), "r"(cy), "r"(cz), "r"(mbar)
        : "memory");
}
#define MBARRIER_INIT(mbar_addr, count) \
    asm volatile("mbarrier.init.shared.b64 [%0], %1;" \
        :: "r"((uint32_t)(mbar_addr)), "r"((uint32_t)(count)) : "memory")
#define MBARRIER_EXPECT_TX(mbar_addr, tx_bytes) \
    asm volatile("mbarrier.arrive.expect_tx.shared.b64 _, [%0], %1;" \
        :: "r"((uint32_t)(mbar_addr)), "r"((uint32_t)(tx_bytes)) : "memory")
#define MBARRIER_WAIT_PARITY(mbar_smem_addr, phase_parity) do { \
    uint32_t _mbar = (uint32_t)(mbar_smem_addr); \
    uint32_t _parity = (uint32_t)(phase_parity); \
    uint32_t _done; \
    asm volatile( \
        "{\n\t.reg .pred p;\n\t" \
        "mbarrier.try_wait.parity.acquire.cta.shared::cta.b64 p, [%1], %2;\n\t" \
        "selp.b32 %0, 1, 0, p;\n\t}" \
        : "=r"(_done) : "r"(_mbar), "r"(_parity) : "memory"); \
    if (!_done) { \
        asm volatile( \
            "{\n\t.reg .pred P1;\n\t" \
            "WAIT_LOOP_%=:\n\t" \
            "mbarrier.try_wait.parity.acquire.cta.shared::cta.b64 P1, [%0], %1, 0x989680;\n\t" \
            "@P1 bra.uni WAIT_DONE_%=;\n\t" \
            "bra.uni WAIT_LOOP_%=;\n\t" \
            "WAIT_DONE_%=:\n\t}" \
            :: "r"(_mbar), "r"(_parity) : "memory"); \
    } \
} while(0)

__device__ __forceinline__ uint32_t swz128(uint32_t b) {
    return b ^ ((b >> 3) & 0x70);
}

// ---------------------------------------------------------------------------
// Kernel 1 (fused, vectorized): Givens-rotate Q into q, k (row-major [S,D])
// and v TRANSPOSED ([b][d][s]).  Each thread handles 4 d-elements (2 pairs):
// float4 Q loads, uint2 (4xhalf) q/k stores, half2 v^T stores.
// Tile: 128 d x 32 s, block (32,8).
// ---------------------------------------------------------------------------
__global__ __launch_bounds__(256) void prep_kernel(const float* __restrict__ Q,
                                                   const float* __restrict__ rot_w) {
    __shared__ __half th[128][33];
    int d0 = blockIdx.x * 128, s0 = blockIdx.y * 32, b = blockIdx.z;
    int tx = threadIdx.x, ty = threadIdx.y;
    int tid = ty * 32 + tx;
    int e0 = d0 + 4 * tx;                       // first of 4 d-elements

    // rotation coefficients: float4 = (c0, s0, c1, s1) for the two pairs
    float4 rq = *(const float4*)(rot_w + e0);
    float4 rk = *(const float4*)(rot_w + DD + e0);
    float4 rv = *(const float4*)(rot_w + 2 * DD + e0);
    {
        float i;
        i = rsqrtf(rq.x * rq.x + rq.y * rq.y); rq.x *= i; rq.y *= i;
        i = rsqrtf(rq.z * rq.z + rq.w * rq.w); rq.z *= i; rq.w *= i;
        i = rsqrtf(rk.x * rk.x + rk.y * rk.y); rk.x *= i; rk.y *= i;
        i = rsqrtf(rk.z * rk.z + rk.w * rk.w); rk.z *= i; rk.w *= i;
        i = rsqrtf(rv.x * rv.x + rv.y * rv.y); rv.x *= i; rv.y *= i;
        i = rsqrtf(rv.z * rv.z + rv.w * rv.w); rv.z *= i; rv.w *= i;
    }

#pragma unroll
    for (int r = 0; r < 4; r++) {
        int srow = s0 + ty + 8 * r;
        size_t off = ((size_t)b * SS + srow) * DD + e0;
        float4 x = *(const float4*)(Q + off);
        // q
        {
            float y0 = rq.x * x.x - rq.y * x.y;
            float y1 = rq.x * x.y + rq.y * x.x;
            float y2 = rq.z * x.z - rq.w * x.w;
            float y3 = rq.z * x.w + rq.w * x.z;
            __half2 h01 = __floats2half2_rn(y0, y1);
            __half2 h23 = __floats2half2_rn(y2, y3);
            uint2 pk = make_uint2(*(uint32_t*)&h01, *(uint32_t*)&h23);
            *(uint2*)(g_qh + off) = pk;
        }
        // k
        {
            float y0 = rk.x * x.x - rk.y * x.y;
            float y1 = rk.x * x.y + rk.y * x.x;
            float y2 = rk.z * x.z - rk.w * x.w;
            float y3 = rk.z * x.w + rk.w * x.z;
            __half2 h01 = __floats2half2_rn(y0, y1);
            __half2 h23 = __floats2half2_rn(y2, y3);
            uint2 pk = make_uint2(*(uint32_t*)&h01, *(uint32_t*)&h23);
            *(uint2*)(g_kh + off) = pk;
        }
        // v -> smem staging (transposed write after barrier)
        {
            float y0 = rv.x * x.x - rv.y * x.y;
            float y1 = rv.x * x.y + rv.y * x.x;
            float y2 = rv.z * x.z - rv.w * x.w;
            float y3 = rv.z * x.w + rv.w * x.z;
            int dl = 4 * tx;
            int sc = ty + 8 * r;
            th[dl + 0][sc] = __float2half(y0);
            th[dl + 1][sc] = __float2half(y1);
            th[dl + 2][sc] = __float2half(y2);
            th[dl + 3][sc] = __float2half(y3);
        }
    }
    __syncthreads();
    // v^T store: 128 d-rows x 16 s-pairs = 2048 half2, 8 per thread
#pragma unroll
    for (int it = 0; it < 8; it++) {
        int idx = tid + it * 256;
        int d = idx >> 4;
        int sp = (idx & 15) * 2;
        __half2 v = __halves2half2(th[d][sp], th[d][sp + 1]);
        *(__half2*)(g_vth + ((size_t)b * DD + d0 + d) * SS + s0 + sp) = v;
    }
}

// ---------------------------------------------------------------------------
// TMA-fed fp16 NT GEMM:  C[M,N] = A[M,K] * B[N,K]^T   (proven R11/R16 shape)
// CTA tile 128x128, 256 threads (8 warps, 2m x 4n of 64x32 warp tiles),
// K-chunk 64 halves (128B SW128 box), 3-stage TMA pipeline, 2 CTAs/SM.
// ---------------------------------------------------------------------------
#define CHUNK 64
#define STAGES 3
#define A_BYTES 16384
#define B_BYTES 16384
#define STAGE_BYTES (A_BYTES + B_BYTES)
#define GSMEM (STAGES * STAGE_BYTES)

__global__ __launch_bounds__(256, 2) void gemm_tma_kernel(
    const __grid_constant__ CUtensorMap mA,
    const __grid_constant__ CUtensorMap mB,
    float* __restrict__ C, int K, int ldc, size_t strideC) {
    extern __shared__ __align__(1024) uint8_t sm[];
    __shared__ __align__(8) uint64_t mbar[STAGES];
    uint32_t sbase = smem_u32(sm);
    uint32_t mbase = smem_u32(mbar);

    int tid = threadIdx.x;
    int wid = tid >> 5, lid = tid & 31;
    int wm = wid & 1;
    int wn = wid >> 1;
    int b = blockIdx.z;
    int m0 = blockIdx.y * 128, n0 = blockIdx.x * 128;
    int niter = K / CHUNK;

    if (tid == 0) {
#pragma unroll
        for (int s = 0; s < STAGES; s++) MBARRIER_INIT(mbase + s * 8, 1);
    }
    __syncthreads();

    if (tid == 0) {
#pragma unroll
        for (int p = 0; p < 2; p++) {
            uint32_t mb = mbase + p * 8;
            uint32_t sd = sbase + p * STAGE_BYTES;
            MBARRIER_EXPECT_TX(mb, STAGE_BYTES);
            tma_load_3d(sd, &mA, p * CHUNK, m0, b, mb);
            tma_load_3d(sd + A_BYTES, &mB, p * CHUNK, n0, b, mb);
        }
    }

    uint32_t rowA[4], rowB[2];
#pragma unroll
    for (int am = 0; am < 4; am++)
        rowA[am] = wm * 64 + am * 16 + (lid & 15);
#pragma unroll
    for (int bq = 0; bq < 2; bq++)
        rowB[bq] = wn * 32 + bq * 16 + (lid & 7) + ((lid >> 4) << 3);
    uint32_t kbA = (lid >> 4) * 16;
    uint32_t kbB = ((lid >> 3) & 1) * 16;

    float acc[4][4][4];
#pragma unroll
    for (int i = 0; i < 4; i++)
#pragma unroll
        for (int j = 0; j < 4; j++)
#pragma unroll
            for (int q = 0; q < 4; q++) acc[i][j][q] = 0.0f;

    for (int it = 0; it < niter; it++) {
        if (tid == 0 && it + 2 < niter) {
            int s2 = (it + 2) % 3;
            uint32_t mb = mbase + s2 * 8;
            uint32_t sd = sbase + s2 * STAGE_BYTES;
            MBARRIER_EXPECT_TX(mb, STAGE_BYTES);
            tma_load_3d(sd, &mA, (it + 2) * CHUNK, m0, b, mb);
            tma_load_3d(sd + A_BYTES, &mB, (it + 2) * CHUNK, n0, b, mb);
        }
        int s = it % 3;
        MBARRIER_WAIT_PARITY(mbase + s * 8, (it / 3) & 1);
        uint32_t sA = sbase + s * STAGE_BYTES;
        uint32_t sB = sA + A_BYTES;

#pragma unroll
        for (int ks = 0; ks < 4; ks++) {
            uint32_t koff = ks * 32;
            uint32_t a[4][4], bh[4][2];
#pragma unroll
            for (int am = 0; am < 4; am++)
                ldsm_x4(a[am][0], a[am][1], a[am][2], a[am][3],
                        sA + swz128(rowA[am] * 128 + kbA + koff));
#pragma unroll
            for (int bq = 0; bq < 2; bq++) {
                uint32_t r0, r1, r2, r3;
                ldsm_x4(r0, r1, r2, r3, sB + swz128(rowB[bq] * 128 + kbB + koff));
                bh[bq * 2][0] = r0; bh[bq * 2][1] = r1;
                bh[bq * 2 + 1][0] = r2; bh[bq * 2 + 1][1] = r3;
            }
#pragma unroll
            for (int am = 0; am < 4; am++)
#pragma unroll
                for (int bn = 0; bn < 4; bn++)
                    mma16816(acc[am][bn], a[am], bh[bn]);
        }
        __syncthreads();
    }

    // epilogue
#pragma unroll
    for (int am = 0; am < 4; am++) {
        int row = m0 + wm * 64 + am * 16 + (lid >> 2);
#pragma unroll
        for (int bn = 0; bn < 4; bn++) {
            int col = n0 + wn * 32 + bn * 8 + (lid & 3) * 2;
            float* p0 = C + b * strideC + (size_t)row * ldc + col;
            float* p1 = C + b * strideC + (size_t)(row + 8) * ldc + col;
            *(float2*)p0 = make_float2(acc[am][bn][0], acc[am][bn][1]);
            *(float2*)p1 = make_float2(acc[am][bn][2], acc[am][bn][3]);
        }
    }
}

// ---------------------------------------------------------------------------
// Softmax((2+2x)/scale + bias) == softmax(2x/scale) (shift-invariant).
// Vectorized: 2x float4 loads, 4x half2 stores per thread.
// ---------------------------------------------------------------------------
__global__ __launch_bounds__(256) void softmax_kernel(const float* __restrict__ scale) {
    size_t rowoff = (size_t)blockIdx.x * SS;
    const float4* row4 = (const float4*)(g_sc + rowoff);
    float alpha = 2.0f / scale[0];
    int tid = threadIdx.x;

    float4 v0 = row4[tid];
    float4 v1 = row4[tid + 256];
    float vals[8] = {v0.x * alpha, v0.y * alpha, v0.z * alpha, v0.w * alpha,
                     v1.x * alpha, v1.y * alpha, v1.z * alpha, v1.w * alpha};
    float lmax = vals[0];
#pragma unroll
    for (int i = 1; i < 8; i++) lmax = fmaxf(lmax, vals[i]);

    __shared__ float sred[8];
    __shared__ float sbc;
    float v = lmax;
#pragma unroll
    for (int o = 16; o > 0; o >>= 1) v = fmaxf(v, __shfl_xor_sync(0xffffffffu, v, o));
    if ((tid & 31) == 0) sred[tid >> 5] = v;
    __syncthreads();
    if (tid == 0) {
        float m = sred[0];
#pragma unroll
        for (int i = 1; i < 8; i++) m = fmaxf(m, sred[i]);
        sbc = m;
    }
    __syncthreads();
    float m = sbc;
    float lsum = 0.0f;
#pragma unroll
    for (int i = 0; i < 8; i++) {
        vals[i] = __expf(vals[i] - m);
        lsum += vals[i];
    }
    v = lsum;
#pragma unroll
    for (int o = 16; o > 0; o >>= 1) v += __shfl_xor_sync(0xffffffffu, v, o);
    __syncthreads();
    if ((tid & 31) == 0) sred[tid >> 5] = v;
    __syncthreads();
    if (tid == 0) {
        float t = 0.0f;
#pragma unroll
        for (int i = 0; i < 8; i++) t += sred[i];
        sbc = 1.0f / t;
    }
    __syncthreads();
    float inv = sbc;

    __half2* out2 = (__half2*)(g_ph + rowoff);
#pragma unroll
    for (int j = 0; j < 2; j++) {
        __half2 h0 = __floats2half2_rn(vals[j * 4 + 0] * inv, vals[j * 4 + 1] * inv);
        __half2 h1 = __floats2half2_rn(vals[j * 4 + 2] * inv, vals[j * 4 + 3] * inv);
        int base = (tid + j * 256) * 2;
        out2[base] = h0;
        out2[base + 1] = h1;
    }
}

// ---------------------------------------------------------------------------
// Row L2 normalization: exactly one float4 per thread (1024 = 256*4).
// ---------------------------------------------------------------------------
__global__ __launch_bounds__(256) void normalize_kernel(float* __restrict__ out) {
    float4* row4 = (float4*)(out + (size_t)blockIdx.x * DD);
    int tid = threadIdx.x;
    float4 x = row4[tid];
    float ss = x.x * x.x + x.y * x.y + x.z * x.z + x.w * x.w;

    __shared__ float sred[8];
    __shared__ float sbc;
    float r = ss;
#pragma unroll
    for (int o = 16; o > 0; o >>= 1) r += __shfl_xor_sync(0xffffffffu, r, o);
    if ((tid & 31) == 0) sred[tid >> 5] = r;
    __syncthreads();
    if (tid == 0) {
        float t = 0.0f;
#pragma unroll
        for (int i = 0; i < 8; i++) t += sred[i];
        sbc = rsqrtf(fmaxf(fabsf(t), 1e-8f));
    }
    __syncthreads();
    float inv = sbc;
    x.x *= inv; x.y *= inv; x.z *= inv; x.w *= inv;
    row4[tid] = x;
}

// ---------------------------------------------------------------------------
// Host: tensormap encoding via runtime-resolved driver entry point
// ---------------------------------------------------------------------------
typedef CUresult (*EncodeFn)(
    CUtensorMap*, CUtensorMapDataType, cuuint32_t, void*,
    const cuuint64_t*, const cuuint64_t*, const cuuint32_t*, const cuuint32_t*,
    CUtensorMapInterleave, CUtensorMapSwizzle, CUtensorMapL2promotion,
    CUtensorMapFloatOOBfill);

static void encode_map(EncodeFn enc, CUtensorMap* m, void* ptr,
                       uint64_t d0, uint64_t d1, uint64_t d2,
                       uint32_t box0, uint32_t box1) {
    cuuint64_t dims[3] = {d0, d1, d2};
    cuuint64_t strides[2] = {d0 * 2, d0 * d1 * 2};
    cuuint32_t box[3] = {box0, box1, 1};
    cuuint32_t es[3] = {1, 1, 1};
    enc(m, CU_TENSOR_MAP_DATA_TYPE_FLOAT16, 3, ptr, dims, strides, box, es,
        CU_TENSOR_MAP_INTERLEAVE_NONE, CU_TENSOR_MAP_SWIZZLE_128B,
        CU_TENSOR_MAP_L2_PROMOTION_L2_128B, CU_TENSOR_MAP_FLOAT_OOB_FILL_NONE);
}

extern "C" void kernel_launch(void* const* d_in, const int* in_sizes, int n_in,
                              void* d_out, int out_size) {
    (void)in_sizes; (void)n_in; (void)out_size;
    const float* Q     = (const float*)d_in[0];
    const float* rot_w = (const float*)d_in[1];
    const float* scale = (const float*)d_in[2];
    float* out = (float*)d_out;

    void* fp = nullptr;
    cudaDriverEntryPointQueryResult qr;
    cudaGetDriverEntryPoint("cuTensorMapEncodeTiled", &fp, cudaEnableDefault, &qr);
    EncodeFn enc = (EncodeFn)fp;

    void *p_qh, *p_kh, *p_vth, *p_sc, *p_ph;
    cudaGetSymbolAddress(&p_qh, g_qh);
    cudaGetSymbolAddress(&p_kh, g_kh);
    cudaGetSymbolAddress(&p_vth, g_vth);
    cudaGetSymbolAddress(&p_sc, g_sc);
    cudaGetSymbolAddress(&p_ph, g_ph);

    CUtensorMap mQKa, mQKb, mPVa, mPVb;
    encode_map(enc, &mQKa, p_qh, DD, SS, BB, CHUNK, 128);   // A: q [S,D]
    encode_map(enc, &mQKb, p_kh, DD, SS, BB, CHUNK, 128);   // B: k [S,D]
    encode_map(enc, &mPVa, p_ph, SS, SS, BB, CHUNK, 128);   // A: p [S,S]
    encode_map(enc, &mPVb, p_vth, SS, DD, BB, CHUNK, 128);  // B: v^T [D,S]

    cudaFuncSetAttribute(gemm_tma_kernel,
                         cudaFuncAttributeMaxDynamicSharedMemorySize, GSMEM);

    prep_kernel<<<dim3(DD / 128, SS / 32, BB), dim3(32, 8)>>>(Q, rot_w);

    gemm_tma_kernel<<<dim3(SS / 128, SS / 128, BB), 256, GSMEM>>>(
        mQKa, mQKb, (float*)p_sc, DD, SS, (size_t)SS * SS);

    softmax_kernel<<<BB * SS, 256>>>(scale);

    gemm_tma_kernel<<<dim3(DD / 128, SS / 128, BB), 256, GSMEM>>>(
        mPVa, mPVb, out, SS, DD, (size_t)SS * DD);

    normalize_kernel<<<BB * SS, 256>>>(out);
}